// round 15
// baseline (speedup 1.0000x reference)
#include <cuda_runtime.h>
#include <cuda_bf16.h>
#include <limits.h>

// Scratch for per-batch chirp metadata (generic fallback path only).
#define MAX_BN (32 * 256)
__device__ int g_sn[MAX_BN];
__device__ int g_en[MAX_BN];
__device__ int g_s0[MAX_BN];
__device__ int g_e0[MAX_BN];

// ---------------------------------------------------------------------------
// Kernel 1 (fallback path): per-batch prefix scan over chirp widths.
// ---------------------------------------------------------------------------
__global__ void tb_meta_kernel(const int* __restrict__ xi,
                               const int* __restrict__ Narr,
                               float* __restrict__ out_xi,
                               int n_max)
{
    extern __shared__ int sh[];
    const int b = blockIdx.x;
    const int i = threadIdx.x;

    const int s0 = xi[(b * n_max + i) * 2 + 0];
    const int e0 = xi[(b * n_max + i) * 2 + 1];
    const int Nb = Narr[b];
    const bool valid = (i < Nb);

    int w = e0 - s0;
    if (w < 0) w = 0;
    const int wv = valid ? w : 0;

    sh[i] = wv;
    __syncthreads();
    for (int off = 1; off < n_max; off <<= 1) {
        int v = (i >= off) ? sh[i - off] : 0;
        __syncthreads();
        sh[i] += v;
        __syncthreads();
    }
    const int csum = sh[i];

    const int sn = csum - wv + i;
    const int en = csum + i;

    const int base = b * n_max + i;
    g_sn[base] = sn;
    g_en[base] = en;
    g_s0[base] = s0;
    g_e0[base] = e0;

    out_xi[base * 2 + 0] = valid ? (float)sn : 0.0f;
    out_xi[base * 2 + 1] = valid ? (float)en : 0.0f;
}

// ---------------------------------------------------------------------------
// Column classification from smem metadata (fallback path).
// ---------------------------------------------------------------------------
template<int NMAX>
__device__ __forceinline__ void classify(
    const int* s_sn, const int* s_en, const int* s_s0, const int* s_e0,
    int Nb, int t, int W,
    bool& in_chirp, bool& is_sep, int& src)
{
    int lo = 0, hi = NMAX;
    #pragma unroll
    for (int step = 0; step < 31; step++) {
        if (lo >= hi) break;
        const int mid = (lo + hi) >> 1;
        const int e = (mid < Nb) ? s_en[mid] : INT_MAX;
        if (e <= t) lo = mid + 1; else hi = mid;
    }
    const int i = lo;
    const int ic = min(i, NMAX - 1);

    const int sn_i = s_sn[ic];
    const int en_i = s_en[ic];
    const int s0_i = s_s0[ic];
    const int e0_i = s_e0[ic];

    in_chirp = (i < Nb) && (t >= sn_i) && (en_i > sn_i) && (e0_i > s0_i);
    src = min(max(s0_i + (t - sn_i), 0), W - 1);

    const int jp = min(max(i - 1, 0), NMAX - 1);
    const int en_prev = s_en[jp];
    is_sep = (i >= 1) && (t == en_prev) && ((i - 1) < (Nb - 1)) && (en_prev < W);
}

// ---------------------------------------------------------------------------
// Fused specialized kernel. Closed-form classification when xi is uniform
// (verified per-warp); fallback = warp0 shfl-scan + smem + binary search.
// THIS ROUND: burst depth 32 — each thread owns 32 rows (z-slab of 64,
// ty stride 2), issuing 32 independent LDGs before any STG.
// grid (49, B, 2) = 1568 blocks, block (128,2), 5 blocks/SM (regs ~48).
// ---------------------------------------------------------------------------
template<int ROWS, int WC, int WOUTC, int NMAX>
__global__ __launch_bounds__(256, 5)
void tb_fused_tpl(const float* __restrict__ x,
                  const int* __restrict__ xi,
                  const int* __restrict__ xl,
                  const float* __restrict__ sep_param,
                  const int* __restrict__ Narr,
                  float* __restrict__ out_x,
                  float* __restrict__ out_xi,
                  float* __restrict__ out_xl)
{
    static_assert(NMAX == 128, "warp scan sized for NMAX=128");
    __shared__ int s_sn[NMAX], s_en[NMAX], s_s0[NMAX], s_e0[NMAX];

    const int b = blockIdx.y;
    const int tid = threadIdx.y * 128 + threadIdx.x;
    const int lane = tid & 31;
    const bool emit = (blockIdx.x == 0 && blockIdx.z == 0);

    // ---- every warp: load 4 chirps/lane, test uniformity ----
    const int Nb = __ldg(&Narr[b]);
    const int4* xi4 = (const int4*)(xi + (b * NMAX + lane * 4) * 2);
    const int4 q0 = __ldg(&xi4[0]);   // s0[0],e0[0],s0[1],e0[1]
    const int4 q1 = __ldg(&xi4[1]);   // s0[2],e0[2],s0[3],e0[3]
    int s0v[4] = {q0.x, q0.z, q1.x, q1.z};
    int e0v[4] = {q0.y, q0.w, q1.y, q1.w};

    const int s0_0 = __shfl_sync(0xffffffffu, s0v[0], 0);
    const int s0_1 = __shfl_sync(0xffffffffu, s0v[1], 0);
    const int w0   = __shfl_sync(0xffffffffu, e0v[0] - s0v[0], 0);
    const int step = s0_1 - s0_0;

    bool ok = (w0 > 0);
    #pragma unroll
    for (int k = 0; k < 4; k++) {
        const int idx = lane * 4 + k;
        ok = ok && (e0v[k] - s0v[k] == w0)
                && (s0v[k] == s0_0 + idx * step);
    }
    const bool uniform = __all_sync(0xffffffffu, ok);

    const int t = blockIdx.x * 128 + threadIdx.x;

    bool in_chirp = false, is_sep = false;
    int src = 0;

    if (uniform) {
        const int P = w0 + 1;
        const unsigned c = (unsigned)(t + 1) / (unsigned)P;
        const int i = min((int)c, Nb);
        const int rem = t - i * P;
        in_chirp = (i < Nb) && (rem >= 0);
        is_sep   = (rem == -1) && (i < Nb) && (t < WC);
        src = min(max(s0_0 + i * step + rem, 0), WC - 1);

        if (emit && tid < NMAX) {
            const bool valid = (tid < Nb);
            const int sn = tid * P;
            out_xi[(b * NMAX + tid) * 2 + 0] = valid ? (float)sn : 0.0f;
            out_xi[(b * NMAX + tid) * 2 + 1] = valid ? (float)(sn + w0) : 0.0f;
        }
    } else {
        if (tid < 32) {
            int wv[4], pre[4];
            int run = 0;
            #pragma unroll
            for (int k = 0; k < 4; k++) {
                const int idx = lane * 4 + k;
                int w = e0v[k] - s0v[k];
                if (w < 0) w = 0;
                wv[k] = (idx < Nb) ? w : 0;
                run += wv[k];
                pre[k] = run;
            }
            int tot = run;
            #pragma unroll
            for (int off = 1; off < 32; off <<= 1) {
                int v = __shfl_up_sync(0xffffffffu, tot, off);
                if (lane >= off) tot += v;
            }
            const int base = tot - run;
            #pragma unroll
            for (int k = 0; k < 4; k++) {
                const int idx = lane * 4 + k;
                const int csum = base + pre[k];
                const int sn = csum - wv[k] + idx;
                const int en = csum + idx;
                s_sn[idx] = sn;
                s_en[idx] = en;
                s_s0[idx] = s0v[k];
                s_e0[idx] = e0v[k];
                if (emit) {
                    const bool valid = (idx < Nb);
                    out_xi[(b * NMAX + idx) * 2 + 0] = valid ? (float)sn : 0.0f;
                    out_xi[(b * NMAX + idx) * 2 + 1] = valid ? (float)en : 0.0f;
                }
            }
        }
        __syncthreads();
        classify<NMAX>(s_sn, s_en, s_s0, s_e0, Nb, t, WC, in_chirp, is_sep, src);
    }

    if (t >= WOUTC) return;

    const float fill = is_sep ? sep_param[0] : 0.0f;
    const int ty = threadIdx.y;                 // 0..1
    const int row0 = blockIdx.z * 64 + ty;      // slab base + sub-row

    const float* __restrict__ xp = x + (size_t)b * ROWS * WC + src
                                     + (size_t)row0 * WC;
    float* __restrict__ op = out_x + (size_t)b * ROWS * WOUTC + t
                                   + (size_t)row0 * WOUTC;

    // xl first so the tiny store doesn't delay block exit.
    if (ty == 0 && blockIdx.z == 0) {
        int xlv = in_chirp ? xl[b * WC + src] : (is_sep ? 2 : 0);
        out_xl[(size_t)b * WOUTC + t] = (float)xlv;
    }

    if (in_chirp) {
        float v[32];
        #pragma unroll
        for (int k = 0; k < 32; k++)
            v[k] = __ldcs(xp + (size_t)(2 * k) * WC);

        #pragma unroll
        for (int k = 0; k < 32; k++)
            op[(size_t)(2 * k) * WOUTC] = v[k];
    } else {
        #pragma unroll
        for (int k = 0; k < 32; k++)
            op[(size_t)(2 * k) * WOUTC] = fill;
    }
}

// ---------------------------------------------------------------------------
// Generic fallback main kernel (two-launch path).
// ---------------------------------------------------------------------------
__global__ __launch_bounds__(256, 6)
void tb_main_kernel(const float* __restrict__ x,
                    const int* __restrict__ xl,
                    const float* __restrict__ sep_param,
                    const int* __restrict__ Narr,
                    float* __restrict__ out_x,
                    float* __restrict__ out_xl,
                    int rows, int W, int w_out, int n_max)
{
    __shared__ int s_sn[256], s_en[256], s_s0[256], s_e0[256];
    __shared__ int s_Nb;

    const int b = blockIdx.y;
    const int tid = threadIdx.y * blockDim.x + threadIdx.x;

    if (tid < n_max) {
        const int base = b * n_max + tid;
        s_sn[tid] = g_sn[base];
        s_en[tid] = g_en[base];
        s_s0[tid] = g_s0[base];
        s_e0[tid] = g_e0[base];
    }
    if (tid == 0) s_Nb = Narr[b];
    __syncthreads();

    const int t = blockIdx.x * blockDim.x + threadIdx.x;
    if (t >= w_out) return;

    const int Nb = s_Nb;
    int lo = 0, hi = n_max;
    while (lo < hi) {
        const int mid = (lo + hi) >> 1;
        const int e = (mid < Nb) ? s_en[mid] : INT_MAX;
        if (e <= t) lo = mid + 1; else hi = mid;
    }
    const int i = lo;
    const int ic = min(i, n_max - 1);
    const int sn_i = s_sn[ic], en_i = s_en[ic];
    const int s0_i = s_s0[ic], e0_i = s_e0[ic];
    const bool in_chirp = (i < Nb) && (t >= sn_i) && (en_i > sn_i) && (e0_i > s0_i);
    int src = min(max(s0_i + (t - sn_i), 0), W - 1);
    const int jp = min(max(i - 1, 0), n_max - 1);
    const int en_prev = s_en[jp];
    const bool is_sep = (i >= 1) && (t == en_prev) && ((i - 1) < (Nb - 1)) && (en_prev < W);
    const float fill = is_sep ? sep_param[0] : 0.0f;

    const float* __restrict__ xcol = x + (size_t)b * rows * W + src;
    float* __restrict__ ocol = out_x + (size_t)b * rows * w_out + t;
    const int ystep = blockDim.y;

    if (in_chirp) {
        int h = threadIdx.y;
        for (; h + 7 * ystep < rows; h += 8 * ystep) {
            float v[8];
            #pragma unroll
            for (int k = 0; k < 8; k++)
                v[k] = __ldcs(xcol + (size_t)(h + k * ystep) * W);
            #pragma unroll
            for (int k = 0; k < 8; k++)
                ocol[(size_t)(h + k * ystep) * w_out] = v[k];
        }
        for (; h < rows; h += ystep)
            ocol[(size_t)h * w_out] = __ldcs(xcol + (size_t)h * W);
    } else {
        for (int h = threadIdx.y; h < rows; h += ystep)
            ocol[(size_t)h * w_out] = fill;
    }

    if (threadIdx.y == 0) {
        int xlv = in_chirp ? xl[b * W + src] : (is_sep ? 2 : 0);
        out_xl[(size_t)b * w_out + t] = (float)xlv;
    }
}

// ---------------------------------------------------------------------------
// Launch.
// ---------------------------------------------------------------------------
extern "C" void kernel_launch(void* const* d_in, const int* in_sizes, int n_in,
                              void* d_out, int out_size)
{
    const float* x   = (const float*)d_in[0];
    const int*   xi  = (const int*)  d_in[1];
    const int*   Nn  = (const int*)  d_in[2];
    const int*   xl  = (const int*)  d_in[3];
    const float* sep = (const float*)d_in[4];

    const int B     = in_sizes[2];
    const int n_max = in_sizes[1] / (2 * B);
    const int W     = in_sizes[3] / B;
    const int rows  = in_sizes[0] / (B * W);           // C * H
    const int w_out = (out_size - B * n_max * 2) / (B * (rows + 1));

    float* out_x  = (float*)d_out;
    float* out_xi = out_x + (size_t)B * rows * w_out;
    float* out_xl = out_xi + (size_t)B * n_max * 2;

    if (rows == 128 && W == 8192 && w_out == 6271 && n_max == 128) {
        dim3 block(128, 2);
        dim3 grid((6271 + 127) / 128, 16, 2);       // 49 x 16 x 2 = 1568 blocks
        tb_fused_tpl<128, 8192, 6271, 128><<<grid, block>>>(
            x, xi, xl, sep, Nn, out_x, out_xi, out_xl);
    } else {
        tb_meta_kernel<<<B, n_max, n_max * sizeof(int)>>>(xi, Nn, out_xi, n_max);
        dim3 block(128, 2);
        dim3 grid((w_out + 127) / 128, B);
        tb_main_kernel<<<grid, block>>>(x, xl, sep, Nn, out_x, out_xl,
                                        rows, W, w_out, n_max);
    }
}

// round 16
// speedup vs baseline: 1.4443x; 1.4443x over previous
#include <cuda_runtime.h>
#include <cuda_bf16.h>
#include <limits.h>

// Scratch for per-batch chirp metadata (generic fallback path only).
#define MAX_BN (32 * 256)
__device__ int g_sn[MAX_BN];
__device__ int g_en[MAX_BN];
__device__ int g_s0[MAX_BN];
__device__ int g_e0[MAX_BN];

// ---------------------------------------------------------------------------
// Kernel 1 (fallback path): per-batch prefix scan over chirp widths.
// ---------------------------------------------------------------------------
__global__ void tb_meta_kernel(const int* __restrict__ xi,
                               const int* __restrict__ Narr,
                               float* __restrict__ out_xi,
                               int n_max)
{
    extern __shared__ int sh[];
    const int b = blockIdx.x;
    const int i = threadIdx.x;

    const int s0 = xi[(b * n_max + i) * 2 + 0];
    const int e0 = xi[(b * n_max + i) * 2 + 1];
    const int Nb = Narr[b];
    const bool valid = (i < Nb);

    int w = e0 - s0;
    if (w < 0) w = 0;
    const int wv = valid ? w : 0;

    sh[i] = wv;
    __syncthreads();
    for (int off = 1; off < n_max; off <<= 1) {
        int v = (i >= off) ? sh[i - off] : 0;
        __syncthreads();
        sh[i] += v;
        __syncthreads();
    }
    const int csum = sh[i];

    const int sn = csum - wv + i;
    const int en = csum + i;

    const int base = b * n_max + i;
    g_sn[base] = sn;
    g_en[base] = en;
    g_s0[base] = s0;
    g_e0[base] = e0;

    out_xi[base * 2 + 0] = valid ? (float)sn : 0.0f;
    out_xi[base * 2 + 1] = valid ? (float)en : 0.0f;
}

// ---------------------------------------------------------------------------
// Column classification from smem metadata (fallback path).
// ---------------------------------------------------------------------------
template<int NMAX>
__device__ __forceinline__ void classify(
    const int* s_sn, const int* s_en, const int* s_s0, const int* s_e0,
    int Nb, int t, int W,
    bool& in_chirp, bool& is_sep, int& src)
{
    int lo = 0, hi = NMAX;
    #pragma unroll
    for (int step = 0; step < 31; step++) {
        if (lo >= hi) break;
        const int mid = (lo + hi) >> 1;
        const int e = (mid < Nb) ? s_en[mid] : INT_MAX;
        if (e <= t) lo = mid + 1; else hi = mid;
    }
    const int i = lo;
    const int ic = min(i, NMAX - 1);

    const int sn_i = s_sn[ic];
    const int en_i = s_en[ic];
    const int s0_i = s_s0[ic];
    const int e0_i = s_e0[ic];

    in_chirp = (i < Nb) && (t >= sn_i) && (en_i > sn_i) && (e0_i > s0_i);
    src = min(max(s0_i + (t - sn_i), 0), W - 1);

    const int jp = min(max(i - 1, 0), NMAX - 1);
    const int en_prev = s_en[jp];
    is_sep = (i >= 1) && (t == en_prev) && ((i - 1) < (Nb - 1)) && (en_prev < W);
}

// ---------------------------------------------------------------------------
// Fused specialized kernel (R14 structure = best measured).
// Closed-form classification when xi is uniform (verified per-warp);
// fallback = warp0 shfl-scan + smem + binary search.
// Burst depth 16 (regs=32, no spills). DEFAULT cache policy on loads so x
// stays L2-resident ACROSS graph replays (x + out ~102MB < 126MB L2).
// grid (49, B, 4) = 3136 blocks, block (128,2), 8 blocks/SM.
// ---------------------------------------------------------------------------
template<int ROWS, int WC, int WOUTC, int NMAX>
__global__ __launch_bounds__(256, 8)
void tb_fused_tpl(const float* __restrict__ x,
                  const int* __restrict__ xi,
                  const int* __restrict__ xl,
                  const float* __restrict__ sep_param,
                  const int* __restrict__ Narr,
                  float* __restrict__ out_x,
                  float* __restrict__ out_xi,
                  float* __restrict__ out_xl)
{
    static_assert(NMAX == 128, "warp scan sized for NMAX=128");
    __shared__ int s_sn[NMAX], s_en[NMAX], s_s0[NMAX], s_e0[NMAX];

    const int b = blockIdx.y;
    const int tid = threadIdx.y * 128 + threadIdx.x;
    const int lane = tid & 31;
    const bool emit = (blockIdx.x == 0 && blockIdx.z == 0);

    // ---- every warp: load 4 chirps/lane, test uniformity ----
    const int Nb = __ldg(&Narr[b]);
    const int4* xi4 = (const int4*)(xi + (b * NMAX + lane * 4) * 2);
    const int4 q0 = __ldg(&xi4[0]);   // s0[0],e0[0],s0[1],e0[1]
    const int4 q1 = __ldg(&xi4[1]);   // s0[2],e0[2],s0[3],e0[3]
    int s0v[4] = {q0.x, q0.z, q1.x, q1.z};
    int e0v[4] = {q0.y, q0.w, q1.y, q1.w};

    const int s0_0 = __shfl_sync(0xffffffffu, s0v[0], 0);
    const int s0_1 = __shfl_sync(0xffffffffu, s0v[1], 0);
    const int w0   = __shfl_sync(0xffffffffu, e0v[0] - s0v[0], 0);
    const int step = s0_1 - s0_0;

    bool ok = (w0 > 0);
    #pragma unroll
    for (int k = 0; k < 4; k++) {
        const int idx = lane * 4 + k;
        ok = ok && (e0v[k] - s0v[k] == w0)
                && (s0v[k] == s0_0 + idx * step);
    }
    const bool uniform = __all_sync(0xffffffffu, ok);

    const int t = blockIdx.x * 128 + threadIdx.x;

    bool in_chirp = false, is_sep = false;
    int src = 0;

    if (uniform) {
        const int P = w0 + 1;
        const unsigned c = (unsigned)(t + 1) / (unsigned)P;
        const int i = min((int)c, Nb);
        const int rem = t - i * P;
        in_chirp = (i < Nb) && (rem >= 0);
        is_sep   = (rem == -1) && (i < Nb) && (t < WC);
        src = min(max(s0_0 + i * step + rem, 0), WC - 1);

        if (emit && tid < NMAX) {
            const bool valid = (tid < Nb);
            const int sn = tid * P;
            out_xi[(b * NMAX + tid) * 2 + 0] = valid ? (float)sn : 0.0f;
            out_xi[(b * NMAX + tid) * 2 + 1] = valid ? (float)(sn + w0) : 0.0f;
        }
    } else {
        if (tid < 32) {
            int wv[4], pre[4];
            int run = 0;
            #pragma unroll
            for (int k = 0; k < 4; k++) {
                const int idx = lane * 4 + k;
                int w = e0v[k] - s0v[k];
                if (w < 0) w = 0;
                wv[k] = (idx < Nb) ? w : 0;
                run += wv[k];
                pre[k] = run;
            }
            int tot = run;
            #pragma unroll
            for (int off = 1; off < 32; off <<= 1) {
                int v = __shfl_up_sync(0xffffffffu, tot, off);
                if (lane >= off) tot += v;
            }
            const int base = tot - run;
            #pragma unroll
            for (int k = 0; k < 4; k++) {
                const int idx = lane * 4 + k;
                const int csum = base + pre[k];
                const int sn = csum - wv[k] + idx;
                const int en = csum + idx;
                s_sn[idx] = sn;
                s_en[idx] = en;
                s_s0[idx] = s0v[k];
                s_e0[idx] = e0v[k];
                if (emit) {
                    const bool valid = (idx < Nb);
                    out_xi[(b * NMAX + idx) * 2 + 0] = valid ? (float)sn : 0.0f;
                    out_xi[(b * NMAX + idx) * 2 + 1] = valid ? (float)en : 0.0f;
                }
            }
        }
        __syncthreads();
        classify<NMAX>(s_sn, s_en, s_s0, s_e0, Nb, t, WC, in_chirp, is_sep, src);
    }

    if (t >= WOUTC) return;

    const float fill = is_sep ? sep_param[0] : 0.0f;
    const int ty = threadIdx.y;                 // 0..1
    const int row0 = blockIdx.z * 32 + ty;      // slab base + sub-row

    const float* __restrict__ xp = x + (size_t)b * ROWS * WC + src
                                     + (size_t)row0 * WC;
    float* __restrict__ op = out_x + (size_t)b * ROWS * WOUTC + t
                                   + (size_t)row0 * WOUTC;

    // xl first so the tiny store doesn't delay block exit.
    if (ty == 0 && blockIdx.z == 0) {
        int xlv = in_chirp ? xl[b * WC + src] : (is_sep ? 2 : 0);
        out_xl[(size_t)b * WOUTC + t] = (float)xlv;
    }

    if (in_chirp) {
        float cur[8];
        #pragma unroll
        for (int k = 0; k < 8; k++)
            cur[k] = __ldg(xp + (size_t)(2 * k) * WC);

        float nxt[8];
        #pragma unroll
        for (int k = 0; k < 8; k++)
            nxt[k] = __ldg(xp + (size_t)(16 + 2 * k) * WC);

        #pragma unroll
        for (int k = 0; k < 8; k++)
            op[(size_t)(2 * k) * WOUTC] = cur[k];

        #pragma unroll
        for (int k = 0; k < 8; k++)
            op[(size_t)(16 + 2 * k) * WOUTC] = nxt[k];
    } else {
        #pragma unroll
        for (int k = 0; k < 16; k++)
            op[(size_t)(2 * k) * WOUTC] = fill;
    }
}

// ---------------------------------------------------------------------------
// Generic fallback main kernel (two-launch path).
// ---------------------------------------------------------------------------
__global__ __launch_bounds__(256, 6)
void tb_main_kernel(const float* __restrict__ x,
                    const int* __restrict__ xl,
                    const float* __restrict__ sep_param,
                    const int* __restrict__ Narr,
                    float* __restrict__ out_x,
                    float* __restrict__ out_xl,
                    int rows, int W, int w_out, int n_max)
{
    __shared__ int s_sn[256], s_en[256], s_s0[256], s_e0[256];
    __shared__ int s_Nb;

    const int b = blockIdx.y;
    const int tid = threadIdx.y * blockDim.x + threadIdx.x;

    if (tid < n_max) {
        const int base = b * n_max + tid;
        s_sn[tid] = g_sn[base];
        s_en[tid] = g_en[base];
        s_s0[tid] = g_s0[base];
        s_e0[tid] = g_e0[base];
    }
    if (tid == 0) s_Nb = Narr[b];
    __syncthreads();

    const int t = blockIdx.x * blockDim.x + threadIdx.x;
    if (t >= w_out) return;

    const int Nb = s_Nb;
    int lo = 0, hi = n_max;
    while (lo < hi) {
        const int mid = (lo + hi) >> 1;
        const int e = (mid < Nb) ? s_en[mid] : INT_MAX;
        if (e <= t) lo = mid + 1; else hi = mid;
    }
    const int i = lo;
    const int ic = min(i, n_max - 1);
    const int sn_i = s_sn[ic], en_i = s_en[ic];
    const int s0_i = s_s0[ic], e0_i = s_e0[ic];
    const bool in_chirp = (i < Nb) && (t >= sn_i) && (en_i > sn_i) && (e0_i > s0_i);
    int src = min(max(s0_i + (t - sn_i), 0), W - 1);
    const int jp = min(max(i - 1, 0), n_max - 1);
    const int en_prev = s_en[jp];
    const bool is_sep = (i >= 1) && (t == en_prev) && ((i - 1) < (Nb - 1)) && (en_prev < W);
    const float fill = is_sep ? sep_param[0] : 0.0f;

    const float* __restrict__ xcol = x + (size_t)b * rows * W + src;
    float* __restrict__ ocol = out_x + (size_t)b * rows * w_out + t;
    const int ystep = blockDim.y;

    if (in_chirp) {
        int h = threadIdx.y;
        for (; h + 7 * ystep < rows; h += 8 * ystep) {
            float v[8];
            #pragma unroll
            for (int k = 0; k < 8; k++)
                v[k] = __ldg(xcol + (size_t)(h + k * ystep) * W);
            #pragma unroll
            for (int k = 0; k < 8; k++)
                ocol[(size_t)(h + k * ystep) * w_out] = v[k];
        }
        for (; h < rows; h += ystep)
            ocol[(size_t)h * w_out] = __ldg(xcol + (size_t)h * W);
    } else {
        for (int h = threadIdx.y; h < rows; h += ystep)
            ocol[(size_t)h * w_out] = fill;
    }

    if (threadIdx.y == 0) {
        int xlv = in_chirp ? xl[b * W + src] : (is_sep ? 2 : 0);
        out_xl[(size_t)b * w_out + t] = (float)xlv;
    }
}

// ---------------------------------------------------------------------------
// Launch.
// ---------------------------------------------------------------------------
extern "C" void kernel_launch(void* const* d_in, const int* in_sizes, int n_in,
                              void* d_out, int out_size)
{
    const float* x   = (const float*)d_in[0];
    const int*   xi  = (const int*)  d_in[1];
    const int*   Nn  = (const int*)  d_in[2];
    const int*   xl  = (const int*)  d_in[3];
    const float* sep = (const float*)d_in[4];

    const int B     = in_sizes[2];
    const int n_max = in_sizes[1] / (2 * B);
    const int W     = in_sizes[3] / B;
    const int rows  = in_sizes[0] / (B * W);           // C * H
    const int w_out = (out_size - B * n_max * 2) / (B * (rows + 1));

    float* out_x  = (float*)d_out;
    float* out_xi = out_x + (size_t)B * rows * w_out;
    float* out_xl = out_xi + (size_t)B * n_max * 2;

    if (rows == 128 && W == 8192 && w_out == 6271 && n_max == 128) {
        dim3 block(128, 2);
        dim3 grid((6271 + 127) / 128, 16, 4);       // 49 x 16 x 4 = 3136 blocks
        tb_fused_tpl<128, 8192, 6271, 128><<<grid, block>>>(
            x, xi, xl, sep, Nn, out_x, out_xi, out_xl);
    } else {
        tb_meta_kernel<<<B, n_max, n_max * sizeof(int)>>>(xi, Nn, out_xi, n_max);
        dim3 block(128, 2);
        dim3 grid((w_out + 127) / 128, B);
        tb_main_kernel<<<grid, block>>>(x, xl, sep, Nn, out_x, out_xl,
                                        rows, W, w_out, n_max);
    }
}